// round 11
// baseline (speedup 1.0000x reference)
#include <cuda_runtime.h>
#include <cuda_bf16.h>
#include <cstdint>

#define R 4096
#define F 256
#define K 8
#define CMIN 1e-6f
#define CMAX 1e6f
#define C_BIAS 0.5287663729448977f  /* log2(log2(e)) */

#define BM 128
#define BN 128
#define TILE_B 16384               // one 128row x 128B bf16 tile (BK=64)
#define A_SMEM (4 * TILE_B + 1024)

// Scratch (static device globals — no runtime allocation)
__device__ __align__(16) float g_base[(size_t)R * (size_t)R];  // 64 MB
__device__ __align__(16) float g_S[K * R];
__device__ __align__(16) float g_rs[4 * R];     // sx1 | n2x1 | sx2 | n2x2
__device__ __align__(16) float g_kp[6 * K];     // akt|bkt2|ekc2|lo|hi|nw
__device__ __align__(16) __nv_bfloat16 g_x1h[R * F];
__device__ __align__(16) __nv_bfloat16 g_x1l[R * F];
__device__ __align__(16) __nv_bfloat16 g_x2h[R * F];
__device__ __align__(16) __nv_bfloat16 g_x2l[R * F];

__device__ __forceinline__ uint32_t smem_u32(const void* p) {
    uint32_t a;
    asm("{ .reg .u64 t; cvta.to.shared.u64 t, %1; cvt.u32.u64 %0, t; }"
        : "=r"(a) : "l"(p));
    return a;
}
__device__ __forceinline__ float ex2f(float x) {
    float y;
    asm("ex2.approx.ftz.f32 %0, %1;" : "=f"(y) : "f"(x));
    return y;
}
// e^kv for kv in [0,1]: degree-5 Taylor at 0.5, coeffs e^0.5/i!.
// max abs error ~3.6e-5 (relative <=3.6e-5 since e^kv >= 1).
__device__ __forceinline__ float exp_unit(float kv) {
    float t = kv - 0.5f;
    float p = 0.013739343922501068f;
    p = fmaf(p, t, 0.06869671961250534f);
    p = fmaf(p, t, 0.27478687845002137f);
    p = fmaf(p, t, 0.8243606353500641f);
    p = fmaf(p, t, 1.6487212707001282f);
    p = fmaf(p, t, 1.6487212707001282f);
    return p;
}
__device__ __forceinline__ void ldsm_x4(uint32_t* r, uint32_t addr) {
    asm volatile("ldmatrix.sync.aligned.m8n8.x4.shared.b16 {%0,%1,%2,%3}, [%4];"
                 : "=r"(r[0]), "=r"(r[1]), "=r"(r[2]), "=r"(r[3]) : "r"(addr));
}
__device__ __forceinline__ void mma16816(float* c, const uint32_t* a,
                                         uint32_t b0, uint32_t b1) {
    asm volatile(
        "mma.sync.aligned.m16n8k16.row.col.f32.bf16.bf16.f32 "
        "{%0,%1,%2,%3}, {%4,%5,%6,%7}, {%8,%9}, {%0,%1,%2,%3};"
        : "+f"(c[0]), "+f"(c[1]), "+f"(c[2]), "+f"(c[3])
        : "r"(a[0]), "r"(a[1]), "r"(a[2]), "r"(a[3]), "r"(b0), "r"(b1));
}

// ---------------------------------------------------------------------------
// Per-k constants. arg = dist*ekc2 + C_BIAS, ekc2 = -log2e/(2 sigma^2) < 0.
// e^kv = ex2(ex2(arg)) (kernelA). kernelB uses the poly form without C_BIAS.
// dist >= CMIN <=> arg <= hi (ekc2<0). The CMAX clamp can never bind for this
// data (dist is bounded by ~1e4 << 1e6), so only the hi clamp is applied.
__global__ void params_kernel(const float* __restrict__ sig,
                              const float* __restrict__ mean,
                              const float* __restrict__ sp) {
    if (threadIdx.x == 0) {
        const float L2E = 1.4426950408889634f;
        float w[K];
        float m = -3.4e38f;
        #pragma unroll
        for (int k = 0; k < K; k++) {
            float v = 1.0f / (sp[k] * sp[k]);
            w[k] = v;
            if (v > m) m = v;
        }
        float s = 0.0f;
        #pragma unroll
        for (int k = 0; k < K; k++) { w[k] = __expf(w[k] - m); s += w[k]; }
        float inv_s = 1.0f / s;
        #pragma unroll
        for (int k = 0; k < K; k++) {
            float ekc2 = -L2E / (2.0f * sig[k] * sig[k]);
            float ak   = -2.0f * mean[k];
            float bk   = (float)F * mean[k] * mean[k];
            g_kp[k]         = ak * ekc2;              // akt
            g_kp[K + k]     = bk * ekc2 + C_BIAS;     // bkt2
            g_kp[2 * K + k] = ekc2;
            g_kp[3 * K + k] = CMAX * ekc2 + C_BIAS;   // lo (unused, kept)
            g_kp[4 * K + k] = CMIN * ekc2 + C_BIAS;   // hi
            g_kp[5 * K + k] = w[k] * inv_s;           // normalized weight
        }
    }
}

// ---------------------------------------------------------------------------
// Fused prep: zero g_S; one warp per row of x1/x2 computes the bf16 hi/lo
// split, the row sum, and the row squared norm.
__global__ void __launch_bounds__(256)
prep_kernel(const float* __restrict__ x1, const float* __restrict__ x2) {
    const int gid = blockIdx.x * blockDim.x + threadIdx.x;
    if (gid < K * R) g_S[gid] = 0.0f;

    const int w    = gid >> 5;          // 0 .. 2R-1 (grid sized exactly)
    const int lane = gid & 31;
    const bool is1 = (w < R);
    const int row  = is1 ? w : (w - R);
    const float* x = is1 ? x1 : x2;
    __nv_bfloat16* xh = is1 ? g_x1h : g_x2h;
    __nv_bfloat16* xl = is1 ? g_x1l : g_x2l;

    const float* p = x + (size_t)row * F + lane * 8;
    float4 v0 = *(const float4*)p;
    float4 v1 = *(const float4*)(p + 4);
    float vals[8] = {v0.x, v0.y, v0.z, v0.w, v1.x, v1.y, v1.z, v1.w};

    float s = 0.0f, q = 0.0f;
    __nv_bfloat16 hb[8], lb[8];
    #pragma unroll
    for (int e = 0; e < 8; e++) {
        float v = vals[e];
        s += v;
        q = fmaf(v, v, q);
        __nv_bfloat16 h = __float2bfloat16(v);
        hb[e] = h;
        lb[e] = __float2bfloat16(v - __bfloat162float(h));
    }
    *(uint4*)(xh + (size_t)row * F + lane * 8) = *(const uint4*)hb;
    *(uint4*)(xl + (size_t)row * F + lane * 8) = *(const uint4*)lb;

    #pragma unroll
    for (int o = 16; o > 0; o >>= 1) {
        s += __shfl_xor_sync(0xFFFFFFFFu, s, o);
        q += __shfl_xor_sync(0xFFFFFFFFu, q, o);
    }
    if (lane == 0) {
        int off = is1 ? 0 : 2 * R;
        g_rs[off + row]     = s;
        g_rs[off + R + row] = q;
    }
}

// ---------------------------------------------------------------------------
// Kernel A: 128x128 tile, bf16 split-GEMM (hh+hl+lh) via mma.sync m16n8k16.
// 8 warps in 2(m) x 4(n) grid, 64x32 per warp, fp32 register accumulators.
// Epilogue: base transform + store + double-exp S accumulation.
__global__ void __launch_bounds__(256, 2)
kernelA() {
    extern __shared__ char dynsmem[];
    __shared__ float skp[6 * K];

    const int tid  = threadIdx.x;
    const int wid  = tid >> 5;
    const int lane = tid & 31;
    const int wm = wid & 1;          // m position (0..1) -> 64 rows
    const int wn = wid >> 1;         // n position (0..3) -> 32 cols
    const int ln15 = lane & 15;
    const int hi16 = lane >> 4;
    const int r0 = blockIdx.y * BM;
    const int c0 = blockIdx.x * BN;

    const uint32_t dsb = smem_u32(dynsmem);
    const uint32_t tiles_u = (dsb + 1023u) & ~1023u;
    char* tiles = dynsmem + (tiles_u - dsb);

    if (tid < 6 * K) skp[tid] = g_kp[tid];

    // loader mapping: 128 rows x 64 bf16 tiles, SW128 swizzle
    const int lrow  = tid >> 1;
    const int lcol0 = (tid & 1) * 32;
    const __nv_bfloat16* pah = g_x1h + (size_t)(r0 + lrow) * F + lcol0;
    const __nv_bfloat16* pal = g_x1l + (size_t)(r0 + lrow) * F + lcol0;
    const __nv_bfloat16* pbh = g_x2h + (size_t)(c0 + lrow) * F + lcol0;
    const __nv_bfloat16* pbl = g_x2l + (size_t)(c0 + lrow) * F + lcol0;

    // ldmatrix base addresses (row part; chunk xor added per k-step)
    const uint32_t a_row = (uint32_t)(wm * 64 + ln15) * 128u;
    const uint32_t b_row = (uint32_t)(wn * 32 + ln15) * 128u;
    const uint32_t ah_base = tiles_u + 0 * TILE_B + a_row;
    const uint32_t al_base = tiles_u + 1 * TILE_B + a_row;
    const uint32_t bh_base = tiles_u + 2 * TILE_B + b_row;
    const uint32_t bl_base = tiles_u + 3 * TILE_B + b_row;

    float acc[4][4][4];
    #pragma unroll
    for (int i = 0; i < 4; i++)
        #pragma unroll
        for (int j = 0; j < 4; j++)
            #pragma unroll
            for (int c = 0; c < 4; c++) acc[i][j][c] = 0.0f;

    for (int kc = 0; kc < 4; kc++) {
        const int k0 = kc * 64;
        __syncthreads();
        #pragma unroll
        for (int j = 0; j < 4; j++) {
            uint32_t boff = lrow * 128 + (lcol0 + j * 8) * 2;
            uint32_t sw = boff ^ ((boff >> 3) & 0x70);
            *(uint4*)(tiles + 0 * TILE_B + sw) = *(const uint4*)(pah + k0 + j * 8);
            *(uint4*)(tiles + 1 * TILE_B + sw) = *(const uint4*)(pal + k0 + j * 8);
            *(uint4*)(tiles + 2 * TILE_B + sw) = *(const uint4*)(pbh + k0 + j * 8);
            *(uint4*)(tiles + 3 * TILE_B + sw) = *(const uint4*)(pbl + k0 + j * 8);
        }
        __syncthreads();

        #pragma unroll
        for (int ks = 0; ks < 4; ks++) {
            const uint32_t q = (uint32_t)(((ks * 2 + hi16) ^ (ln15 & 7)) * 16);
            uint32_t ah[4][4], bh[2][4], bl[2][4];
            #pragma unroll
            for (int mf = 0; mf < 4; mf++)
                ldsm_x4(ah[mf], ah_base + q + mf * 2048);
            #pragma unroll
            for (int n2 = 0; n2 < 2; n2++)
                ldsm_x4(bh[n2], bh_base + q + n2 * 2048);
            #pragma unroll
            for (int n2 = 0; n2 < 2; n2++)
                ldsm_x4(bl[n2], bl_base + q + n2 * 2048);

            // hh
            #pragma unroll
            for (int mf = 0; mf < 4; mf++)
                #pragma unroll
                for (int nf = 0; nf < 4; nf++)
                    mma16816(acc[mf][nf], ah[mf],
                             bh[nf >> 1][nf & 1], bh[nf >> 1][(nf & 1) + 2]);
            // hl
            #pragma unroll
            for (int mf = 0; mf < 4; mf++)
                #pragma unroll
                for (int nf = 0; nf < 4; nf++)
                    mma16816(acc[mf][nf], ah[mf],
                             bl[nf >> 1][nf & 1], bl[nf >> 1][(nf & 1) + 2]);
            // lh (A-lo overwrites A-hi registers)
            #pragma unroll
            for (int mf = 0; mf < 4; mf++)
                ldsm_x4(ah[mf], al_base + q + mf * 2048);
            #pragma unroll
            for (int mf = 0; mf < 4; mf++)
                #pragma unroll
                for (int nf = 0; nf < 4; nf++)
                    mma16816(acc[mf][nf], ah[mf],
                             bh[nf >> 1][nf & 1], bh[nf >> 1][(nf & 1) + 2]);
        }
    }

    // ---- epilogue ----
    // fragment layout: elem (mf, nf, half, e):
    //   row = r0 + wm*64 + mf*16 + half*8 + lane/4
    //   col = c0 + wn*32 + nf*8 + (lane&3)*2 + e
    const int rbase = r0 + wm * 64 + (lane >> 2);
    const int cbase = c0 + wn * 32 + (lane & 3) * 2;

    float sx1r8[8], n21r8[8];
    #pragma unroll
    for (int i = 0; i < 8; i++) {
        int row = rbase + (i >> 1) * 16 + (i & 1) * 8;
        sx1r8[i] = g_rs[row];
        n21r8[i] = g_rs[R + row];
    }
    float n22c[8], s2c[8];
    #pragma unroll
    for (int nf = 0; nf < 4; nf++) {
        float2 n2 = *(const float2*)&g_rs[3 * R + cbase + nf * 8];
        float2 s2 = *(const float2*)&g_rs[2 * R + cbase + nf * 8];
        n22c[nf * 2] = n2.x; n22c[nf * 2 + 1] = n2.y;
        s2c[nf * 2]  = s2.x; s2c[nf * 2 + 1]  = s2.y;
    }

    // transform to base and store
    #pragma unroll
    for (int mf = 0; mf < 4; mf++) {
        #pragma unroll
        for (int h = 0; h < 2; h++) {
            int row = rbase + mf * 16 + h * 8;
            float n21 = n21r8[mf * 2 + h];
            #pragma unroll
            for (int nf = 0; nf < 4; nf++) {
                float b0 = n21 + n22c[nf * 2]     - 2.0f * acc[mf][nf][h * 2];
                float b1 = n21 + n22c[nf * 2 + 1] - 2.0f * acc[mf][nf][h * 2 + 1];
                acc[mf][nf][h * 2]     = b0;
                acc[mf][nf][h * 2 + 1] = b1;
                float2 o = {b0, b1};
                *(float2*)&g_base[(size_t)row * R + cbase + nf * 8] = o;
            }
        }
    }

    // S accumulation: per k, per row-fragment, sum over this thread's 8 cols,
    // quad-reduce (lanes sharing a row), atomic to g_S.
    #pragma unroll
    for (int k = 0; k < K; k++) {
        const float akt  = skp[k];
        const float nakt = -akt;
        const float bkt2 = skp[K + k];
        const float ekc2 = skp[2 * K + k];
        const float hi   = skp[4 * K + k];
        #pragma unroll
        for (int mf = 0; mf < 4; mf++) {
            #pragma unroll
            for (int h = 0; h < 2; h++) {
                const float pi = fmaf(sx1r8[mf * 2 + h], akt, bkt2);
                float s = 0.0f;
                #pragma unroll
                for (int nf = 0; nf < 4; nf++) {
                    #pragma unroll
                    for (int e = 0; e < 2; e++) {
                        float arg = fmaf(acc[mf][nf][h * 2 + e], ekc2,
                                         fmaf(s2c[nf * 2 + e], nakt, pi));
                        arg = fminf(arg, hi);
                        s += ex2f(ex2f(arg));   // = exp(kv)
                    }
                }
                s += __shfl_xor_sync(0xFFFFFFFFu, s, 1);
                s += __shfl_xor_sync(0xFFFFFFFFu, s, 2);
                if ((lane & 3) == 0)
                    atomicAdd(&g_S[k * R + rbase + mf * 16 + h * 8], s);
            }
        }
    }
}

// ---------------------------------------------------------------------------
// Kernel B: one block per TWO rows; column-side data shared across rows.
// Second exp via FMA-pipe polynomial (kv in (0,1]); first exp stays on MUFU.
__global__ void __launch_bounds__(256)
kernelB(float* __restrict__ out) {
    const int r0 = blockIdx.x * 2;
    __shared__ float sa[K], se[K], shi[K];
    __shared__ float sw0[K], sw1[K], sp0[K], sp1[K];
    if (threadIdx.x < K) {
        int k = threadIdx.x;
        float akt = g_kp[k];
        float nw  = g_kp[5 * K + k];
        float bkt = g_kp[K + k] - C_BIAS;   // un-bias for the poly path
        sa[k]  = akt;
        se[k]  = g_kp[2 * K + k];
        shi[k] = g_kp[4 * K + k] - C_BIAS;
        sw0[k] = nw / g_S[k * R + r0];
        sw1[k] = nw / g_S[k * R + r0 + 1];
        sp0[k] = fmaf(g_rs[r0],     akt, bkt);
        sp1[k] = fmaf(g_rs[r0 + 1], akt, bkt);
    }
    __syncthreads();

    float nakt[K], ekc2[K], hi[K];
    float wk0[K], wk1[K], pr0[K], pr1[K];
    #pragma unroll
    for (int k = 0; k < K; k++) {
        nakt[k] = -sa[k]; ekc2[k] = se[k]; hi[k] = shi[k];
        wk0[k] = sw0[k]; wk1[k] = sw1[k]; pr0[k] = sp0[k]; pr1[k] = sp1[k];
    }
    const float* brow0 = g_base + (size_t)r0 * R;
    const float* brow1 = g_base + (size_t)(r0 + 1) * R;
    float* orow0 = out + (size_t)r0 * R;
    float* orow1 = out + (size_t)(r0 + 1) * R;

    #pragma unroll
    for (int it = 0; it < R / (256 * 4); it++) {
        int c = (it * 256 + threadIdx.x) * 4;
        float4 s4  = *(const float4*)(g_rs + 2 * R + c);
        float4 b40 = *(const float4*)(brow0 + c);
        float4 b41 = *(const float4*)(brow1 + c);
        const float* cc  = (const float*)&s4;
        const float* bb0 = (const float*)&b40;
        const float* bb1 = (const float*)&b41;
        float o0[4] = {0.0f, 0.0f, 0.0f, 0.0f};
        float o1[4] = {0.0f, 0.0f, 0.0f, 0.0f};
        #pragma unroll
        for (int j = 0; j < 4; j++) {
            #pragma unroll
            for (int k = 0; k < K; k++) {
                float t = cc[j] * nakt[k];            // shared by both rows
                float a0 = fmaf(bb0[j], ekc2[k], t + pr0[k]);
                float a1 = fmaf(bb1[j], ekc2[k], t + pr1[k]);
                a0 = fminf(a0, hi[k]);
                a1 = fminf(a1, hi[k]);
                o0[j] = fmaf(exp_unit(ex2f(a0)), wk0[k], o0[j]);
                o1[j] = fmaf(exp_unit(ex2f(a1)), wk1[k], o1[j]);
            }
        }
        float4 ov0 = {o0[0], o0[1], o0[2], o0[3]};
        float4 ov1 = {o1[0], o1[1], o1[2], o1[3]};
        *(float4*)(orow0 + c) = ov0;
        *(float4*)(orow1 + c) = ov1;
    }
}

// ---------------------------------------------------------------------------
extern "C" void kernel_launch(void* const* d_in, const int* in_sizes, int n_in,
                              void* d_out, int out_size) {
    const float* x1   = (const float*)d_in[0];  // [R, F]
    const float* x2   = (const float*)d_in[1];  // [R, F]
    const float* sig  = (const float*)d_in[2];  // [K]
    const float* mean = (const float*)d_in[3];  // [K]
    const float* sp   = (const float*)d_in[4];  // [K]
    float* out = (float*)d_out;                 // [R, R]

    cudaFuncSetAttribute(kernelA, cudaFuncAttributeMaxDynamicSharedMemorySize,
                         A_SMEM);

    params_kernel<<<1, 32>>>(sig, mean, sp);
    prep_kernel<<<(2 * R) / 8, 256>>>(x1, x2);   // zero S + split + stats

    dim3 gridA(R / BN, R / BM);
    kernelA<<<gridA, 256, A_SMEM>>>();

    kernelB<<<R / 2, 256>>>(out);
}

// round 12
// speedup vs baseline: 1.3877x; 1.3877x over previous
#include <cuda_runtime.h>
#include <cuda_bf16.h>
#include <cstdint>

#define R 4096
#define F 256
#define K 8
#define CMIN 1e-6f
#define CMAX 1e6f
#define C_BIAS 0.5287663729448977f  /* log2(log2(e)) */

#define BM 128
#define BN 128
#define TILE_B 16384               // one 128row x 128B bf16 tile (BK=64)
#define A_SMEM (4 * TILE_B + 1024)

// Scratch (static device globals — no runtime allocation)
__device__ __align__(16) float g_base[(size_t)R * (size_t)R];  // 64 MB
__device__ __align__(16) float g_S[K * R];
__device__ __align__(16) float g_rs[4 * R];     // sx1 | n2x1 | sx2 | n2x2
__device__ __align__(16) float g_kc[5 * K];     // compacted: akt|bkt2|ekc2|hi|nw
__device__ int g_nact;
__device__ __align__(16) __nv_bfloat16 g_x1h[R * F];
__device__ __align__(16) __nv_bfloat16 g_x1l[R * F];
__device__ __align__(16) __nv_bfloat16 g_x2h[R * F];
__device__ __align__(16) __nv_bfloat16 g_x2l[R * F];

__device__ __forceinline__ uint32_t smem_u32(const void* p) {
    uint32_t a;
    asm("{ .reg .u64 t; cvta.to.shared.u64 t, %1; cvt.u32.u64 %0, t; }"
        : "=r"(a) : "l"(p));
    return a;
}
__device__ __forceinline__ float ex2f(float x) {
    float y;
    asm("ex2.approx.ftz.f32 %0, %1;" : "=f"(y) : "f"(x));
    return y;
}
__device__ __forceinline__ void ldsm_x4(uint32_t* r, uint32_t addr) {
    asm volatile("ldmatrix.sync.aligned.m8n8.x4.shared.b16 {%0,%1,%2,%3}, [%4];"
                 : "=r"(r[0]), "=r"(r[1]), "=r"(r[2]), "=r"(r[3]) : "r"(addr));
}
__device__ __forceinline__ void mma16816(float* c, const uint32_t* a,
                                         uint32_t b0, uint32_t b1) {
    asm volatile(
        "mma.sync.aligned.m16n8k16.row.col.f32.bf16.bf16.f32 "
        "{%0,%1,%2,%3}, {%4,%5,%6,%7}, {%8,%9}, {%0,%1,%2,%3};"
        : "+f"(c[0]), "+f"(c[1]), "+f"(c[2]), "+f"(c[3])
        : "r"(a[0]), "r"(a[1]), "r"(a[2]), "r"(a[3]), "r"(b0), "r"(b1));
}

// ---------------------------------------------------------------------------
// Per-k constants, COMPACTED to the k's whose softmax weight exceeds 1e-7
// (dropped k's contribute < 1e-7 relative to the output; weights are a
// softmax of 1/sp^2 which is near-one-hot for generic sp).
// arg = dist*ekc2 + C_BIAS, ekc2 = -log2e/(2 sigma^2) < 0; e^kv = ex2(ex2(arg)).
// dist >= CMIN <=> arg <= hi. CMAX clamp never binds (dist << 1e6).
__global__ void params_kernel(const float* __restrict__ sig,
                              const float* __restrict__ mean,
                              const float* __restrict__ sp) {
    if (threadIdx.x == 0) {
        const float L2E = 1.4426950408889634f;
        float w[K];
        float m = -3.4e38f;
        #pragma unroll
        for (int k = 0; k < K; k++) {
            float v = 1.0f / (sp[k] * sp[k]);
            w[k] = v;
            if (v > m) m = v;
        }
        float s = 0.0f;
        #pragma unroll
        for (int k = 0; k < K; k++) { w[k] = __expf(w[k] - m); s += w[k]; }
        float inv_s = 1.0f / s;
        int na = 0;
        for (int k = 0; k < K; k++) {
            float nw = w[k] * inv_s;
            if (nw > 1e-7f) {
                float ekc2 = -L2E / (2.0f * sig[k] * sig[k]);
                float ak   = -2.0f * mean[k];
                float bk   = (float)F * mean[k] * mean[k];
                g_kc[na]         = ak * ekc2;              // akt
                g_kc[K + na]     = bk * ekc2 + C_BIAS;     // bkt2
                g_kc[2 * K + na] = ekc2;
                g_kc[3 * K + na] = CMIN * ekc2 + C_BIAS;   // hi
                g_kc[4 * K + na] = nw;                     // weight
                na++;
            }
        }
        g_nact = na;
    }
}

// ---------------------------------------------------------------------------
// Fused prep: zero g_S; one warp per row of x1/x2 computes the bf16 hi/lo
// split, the row sum, and the row squared norm.
__global__ void __launch_bounds__(256)
prep_kernel(const float* __restrict__ x1, const float* __restrict__ x2) {
    const int gid = blockIdx.x * blockDim.x + threadIdx.x;
    if (gid < K * R) g_S[gid] = 0.0f;

    const int w    = gid >> 5;          // 0 .. 2R-1 (grid sized exactly)
    const int lane = gid & 31;
    const bool is1 = (w < R);
    const int row  = is1 ? w : (w - R);
    const float* x = is1 ? x1 : x2;
    __nv_bfloat16* xh = is1 ? g_x1h : g_x2h;
    __nv_bfloat16* xl = is1 ? g_x1l : g_x2l;

    const float* p = x + (size_t)row * F + lane * 8;
    float4 v0 = *(const float4*)p;
    float4 v1 = *(const float4*)(p + 4);
    float vals[8] = {v0.x, v0.y, v0.z, v0.w, v1.x, v1.y, v1.z, v1.w};

    float s = 0.0f, q = 0.0f;
    __nv_bfloat16 hb[8], lb[8];
    #pragma unroll
    for (int e = 0; e < 8; e++) {
        float v = vals[e];
        s += v;
        q = fmaf(v, v, q);
        __nv_bfloat16 h = __float2bfloat16(v);
        hb[e] = h;
        lb[e] = __float2bfloat16(v - __bfloat162float(h));
    }
    *(uint4*)(xh + (size_t)row * F + lane * 8) = *(const uint4*)hb;
    *(uint4*)(xl + (size_t)row * F + lane * 8) = *(const uint4*)lb;

    #pragma unroll
    for (int o = 16; o > 0; o >>= 1) {
        s += __shfl_xor_sync(0xFFFFFFFFu, s, o);
        q += __shfl_xor_sync(0xFFFFFFFFu, q, o);
    }
    if (lane == 0) {
        int off = is1 ? 0 : 2 * R;
        g_rs[off + row]     = s;
        g_rs[off + R + row] = q;
    }
}

// ---------------------------------------------------------------------------
// Kernel A: 128x128 tile, bf16 split-GEMM (hh+hl+lh) via mma.sync m16n8k16.
// 8 warps in 2(m) x 4(n) grid, 64x32 per warp, fp32 register accumulators.
// Epilogue: base transform + store + double-exp S accumulation over the
// ACTIVE k's only (dynamic loop, consts from shared).
__global__ void __launch_bounds__(256, 2)
kernelA() {
    extern __shared__ char dynsmem[];
    __shared__ float skc[5 * K];
    __shared__ int s_na;

    const int tid  = threadIdx.x;
    const int wid  = tid >> 5;
    const int lane = tid & 31;
    const int wm = wid & 1;          // m position (0..1) -> 64 rows
    const int wn = wid >> 1;         // n position (0..3) -> 32 cols
    const int ln15 = lane & 15;
    const int hi16 = lane >> 4;
    const int r0 = blockIdx.y * BM;
    const int c0 = blockIdx.x * BN;

    const uint32_t dsb = smem_u32(dynsmem);
    const uint32_t tiles_u = (dsb + 1023u) & ~1023u;
    char* tiles = dynsmem + (tiles_u - dsb);

    if (tid < 5 * K) skc[tid] = g_kc[tid];
    if (tid == 0) s_na = g_nact;

    // loader mapping: 128 rows x 64 bf16 tiles, SW128 swizzle
    const int lrow  = tid >> 1;
    const int lcol0 = (tid & 1) * 32;
    const __nv_bfloat16* pah = g_x1h + (size_t)(r0 + lrow) * F + lcol0;
    const __nv_bfloat16* pal = g_x1l + (size_t)(r0 + lrow) * F + lcol0;
    const __nv_bfloat16* pbh = g_x2h + (size_t)(c0 + lrow) * F + lcol0;
    const __nv_bfloat16* pbl = g_x2l + (size_t)(c0 + lrow) * F + lcol0;

    // ldmatrix base addresses (row part; chunk xor added per k-step)
    const uint32_t a_row = (uint32_t)(wm * 64 + ln15) * 128u;
    const uint32_t b_row = (uint32_t)(wn * 32 + ln15) * 128u;
    const uint32_t ah_base = tiles_u + 0 * TILE_B + a_row;
    const uint32_t al_base = tiles_u + 1 * TILE_B + a_row;
    const uint32_t bh_base = tiles_u + 2 * TILE_B + b_row;
    const uint32_t bl_base = tiles_u + 3 * TILE_B + b_row;

    float acc[4][4][4];
    #pragma unroll
    for (int i = 0; i < 4; i++)
        #pragma unroll
        for (int j = 0; j < 4; j++)
            #pragma unroll
            for (int c = 0; c < 4; c++) acc[i][j][c] = 0.0f;

    for (int kc = 0; kc < 4; kc++) {
        const int k0 = kc * 64;
        __syncthreads();
        #pragma unroll
        for (int j = 0; j < 4; j++) {
            uint32_t boff = lrow * 128 + (lcol0 + j * 8) * 2;
            uint32_t sw = boff ^ ((boff >> 3) & 0x70);
            *(uint4*)(tiles + 0 * TILE_B + sw) = *(const uint4*)(pah + k0 + j * 8);
            *(uint4*)(tiles + 1 * TILE_B + sw) = *(const uint4*)(pal + k0 + j * 8);
            *(uint4*)(tiles + 2 * TILE_B + sw) = *(const uint4*)(pbh + k0 + j * 8);
            *(uint4*)(tiles + 3 * TILE_B + sw) = *(const uint4*)(pbl + k0 + j * 8);
        }
        __syncthreads();

        #pragma unroll
        for (int ks = 0; ks < 4; ks++) {
            const uint32_t q = (uint32_t)(((ks * 2 + hi16) ^ (ln15 & 7)) * 16);
            uint32_t ah[4][4], bh[2][4], bl[2][4];
            #pragma unroll
            for (int mf = 0; mf < 4; mf++)
                ldsm_x4(ah[mf], ah_base + q + mf * 2048);
            #pragma unroll
            for (int n2 = 0; n2 < 2; n2++)
                ldsm_x4(bh[n2], bh_base + q + n2 * 2048);
            #pragma unroll
            for (int n2 = 0; n2 < 2; n2++)
                ldsm_x4(bl[n2], bl_base + q + n2 * 2048);

            // hh
            #pragma unroll
            for (int mf = 0; mf < 4; mf++)
                #pragma unroll
                for (int nf = 0; nf < 4; nf++)
                    mma16816(acc[mf][nf], ah[mf],
                             bh[nf >> 1][nf & 1], bh[nf >> 1][(nf & 1) + 2]);
            // hl
            #pragma unroll
            for (int mf = 0; mf < 4; mf++)
                #pragma unroll
                for (int nf = 0; nf < 4; nf++)
                    mma16816(acc[mf][nf], ah[mf],
                             bl[nf >> 1][nf & 1], bl[nf >> 1][(nf & 1) + 2]);
            // lh (A-lo overwrites A-hi registers)
            #pragma unroll
            for (int mf = 0; mf < 4; mf++)
                ldsm_x4(ah[mf], al_base + q + mf * 2048);
            #pragma unroll
            for (int mf = 0; mf < 4; mf++)
                #pragma unroll
                for (int nf = 0; nf < 4; nf++)
                    mma16816(acc[mf][nf], ah[mf],
                             bh[nf >> 1][nf & 1], bh[nf >> 1][(nf & 1) + 2]);
        }
    }

    // ---- epilogue ----
    // fragment layout: elem (mf, nf, half, e):
    //   row = r0 + wm*64 + mf*16 + half*8 + lane/4
    //   col = c0 + wn*32 + nf*8 + (lane&3)*2 + e
    const int rbase = r0 + wm * 64 + (lane >> 2);
    const int cbase = c0 + wn * 32 + (lane & 3) * 2;

    float sx1r8[8], n21r8[8];
    #pragma unroll
    for (int i = 0; i < 8; i++) {
        int row = rbase + (i >> 1) * 16 + (i & 1) * 8;
        sx1r8[i] = g_rs[row];
        n21r8[i] = g_rs[R + row];
    }
    float n22c[8], s2c[8];
    #pragma unroll
    for (int nf = 0; nf < 4; nf++) {
        float2 n2 = *(const float2*)&g_rs[3 * R + cbase + nf * 8];
        float2 s2 = *(const float2*)&g_rs[2 * R + cbase + nf * 8];
        n22c[nf * 2] = n2.x; n22c[nf * 2 + 1] = n2.y;
        s2c[nf * 2]  = s2.x; s2c[nf * 2 + 1]  = s2.y;
    }

    // transform to base and store
    #pragma unroll
    for (int mf = 0; mf < 4; mf++) {
        #pragma unroll
        for (int h = 0; h < 2; h++) {
            int row = rbase + mf * 16 + h * 8;
            float n21 = n21r8[mf * 2 + h];
            #pragma unroll
            for (int nf = 0; nf < 4; nf++) {
                float b0 = n21 + n22c[nf * 2]     - 2.0f * acc[mf][nf][h * 2];
                float b1 = n21 + n22c[nf * 2 + 1] - 2.0f * acc[mf][nf][h * 2 + 1];
                acc[mf][nf][h * 2]     = b0;
                acc[mf][nf][h * 2 + 1] = b1;
                float2 o = {b0, b1};
                *(float2*)&g_base[(size_t)row * R + cbase + nf * 8] = o;
            }
        }
    }

    // S accumulation over ACTIVE k's: per kk, per row-fragment, sum this
    // thread's 8 cols, quad-reduce, atomic to g_S (compacted kk index).
    const int na = s_na;
    for (int kk = 0; kk < na; kk++) {
        const float akt  = skc[kk];
        const float nakt = -akt;
        const float bkt2 = skc[K + kk];
        const float ekc2 = skc[2 * K + kk];
        const float hi   = skc[3 * K + kk];
        #pragma unroll
        for (int mf = 0; mf < 4; mf++) {
            #pragma unroll
            for (int h = 0; h < 2; h++) {
                const float pi = fmaf(sx1r8[mf * 2 + h], akt, bkt2);
                float s = 0.0f;
                #pragma unroll
                for (int nf = 0; nf < 4; nf++) {
                    #pragma unroll
                    for (int e = 0; e < 2; e++) {
                        float arg = fmaf(acc[mf][nf][h * 2 + e], ekc2,
                                         fmaf(s2c[nf * 2 + e], nakt, pi));
                        arg = fminf(arg, hi);
                        s += ex2f(ex2f(arg));   // = exp(kv)
                    }
                }
                s += __shfl_xor_sync(0xFFFFFFFFu, s, 1);
                s += __shfl_xor_sync(0xFFFFFFFFu, s, 2);
                if ((lane & 3) == 0)
                    atomicAdd(&g_S[kk * R + rbase + mf * 16 + h * 8], s);
            }
        }
    }
}

// ---------------------------------------------------------------------------
// Kernel B: one block per TWO rows; column-side data shared across rows.
// Dynamic loop over active k's; double-ex2 on MUFU (issue-optimal form).
__global__ void __launch_bounds__(256)
kernelB(float* __restrict__ out) {
    const int r0 = blockIdx.x * 2;
    __shared__ float sa[K], se[K], shi[K];
    __shared__ float sw0[K], sw1[K], sp0[K], sp1[K];
    __shared__ int s_na;
    if (threadIdx.x == 0) s_na = g_nact;
    if (threadIdx.x < K) {
        int k = threadIdx.x;
        float akt = g_kc[k];
        float nw  = g_kc[4 * K + k];
        float bkt2 = g_kc[K + k];
        sa[k]  = akt;
        se[k]  = g_kc[2 * K + k];
        shi[k] = g_kc[3 * K + k];
        sw0[k] = nw / g_S[k * R + r0];
        sw1[k] = nw / g_S[k * R + r0 + 1];
        sp0[k] = fmaf(g_rs[r0],     akt, bkt2);
        sp1[k] = fmaf(g_rs[r0 + 1], akt, bkt2);
    }
    __syncthreads();

    const int na = s_na;
    const float* brow0 = g_base + (size_t)r0 * R;
    const float* brow1 = g_base + (size_t)(r0 + 1) * R;
    float* orow0 = out + (size_t)r0 * R;
    float* orow1 = out + (size_t)(r0 + 1) * R;

    #pragma unroll
    for (int it = 0; it < R / (256 * 4); it++) {
        int c = (it * 256 + threadIdx.x) * 4;
        float4 s4  = *(const float4*)(g_rs + 2 * R + c);
        float4 b40 = *(const float4*)(brow0 + c);
        float4 b41 = *(const float4*)(brow1 + c);
        const float* cc  = (const float*)&s4;
        const float* bb0 = (const float*)&b40;
        const float* bb1 = (const float*)&b41;
        float o0[4] = {0.0f, 0.0f, 0.0f, 0.0f};
        float o1[4] = {0.0f, 0.0f, 0.0f, 0.0f};
        for (int kk = 0; kk < na; kk++) {
            const float nakt = -sa[kk];
            const float ekc2 = se[kk];
            const float hi   = shi[kk];
            const float wk0  = sw0[kk];
            const float wk1  = sw1[kk];
            const float pr0  = sp0[kk];
            const float pr1  = sp1[kk];
            #pragma unroll
            for (int j = 0; j < 4; j++) {
                float t = cc[j] * nakt;               // shared by both rows
                float a0 = fmaf(bb0[j], ekc2, t + pr0);
                float a1 = fmaf(bb1[j], ekc2, t + pr1);
                a0 = fminf(a0, hi);
                a1 = fminf(a1, hi);
                o0[j] = fmaf(ex2f(ex2f(a0)), wk0, o0[j]);
                o1[j] = fmaf(ex2f(ex2f(a1)), wk1, o1[j]);
            }
        }
        float4 ov0 = {o0[0], o0[1], o0[2], o0[3]};
        float4 ov1 = {o1[0], o1[1], o1[2], o1[3]};
        *(float4*)(orow0 + c) = ov0;
        *(float4*)(orow1 + c) = ov1;
    }
}

// ---------------------------------------------------------------------------
extern "C" void kernel_launch(void* const* d_in, const int* in_sizes, int n_in,
                              void* d_out, int out_size) {
    const float* x1   = (const float*)d_in[0];  // [R, F]
    const float* x2   = (const float*)d_in[1];  // [R, F]
    const float* sig  = (const float*)d_in[2];  // [K]
    const float* mean = (const float*)d_in[3];  // [K]
    const float* sp   = (const float*)d_in[4];  // [K]
    float* out = (float*)d_out;                 // [R, R]

    cudaFuncSetAttribute(kernelA, cudaFuncAttributeMaxDynamicSharedMemorySize,
                         A_SMEM);

    params_kernel<<<1, 32>>>(sig, mean, sp);
    prep_kernel<<<(2 * R) / 8, 256>>>(x1, x2);   // zero S + split + stats

    dim3 gridA(R / BN, R / BM);
    kernelA<<<gridA, 256, A_SMEM>>>();

    kernelB<<<R / 2, 256>>>(out);
}